// round 15
// baseline (speedup 1.0000x reference)
#include <cuda_runtime.h>
#include <cuda_bf16.h>
#include <stdint.h>

// FineMatching R14: R13 +
//  - __ldcs on feat0 (read-once) and __stcs on out_sm (write-once): evict-first,
//    protects the L2-prefetched feat1 slab that the GEMM A-loads depend on
//  - ks=0 A-fragment loads hoisted above the stage barrier (in flight during barrier)

#define TPB 256
#define SKE 68    // Ef2 stride floats, [l][k] layout
#define SAF 68    // Aff stride floats
#define SBF 113   // Bff stride floats
#define SCP 68    // colpart stride floats
#define BSTR 144  // feat0 bf16 tile row stride bytes (72 b16)

// byte offsets in dynamic smem
#define B_AFF   0        // 8*68*4  = 2176   (feat0 ch 56..63, [c][l])
#define B_BFF   2176     // 8*113*4 = 3616 -> 5792  (feat1 ch 56..63, [c][r])
#define B_BHI   5792     // feat0 hi bf16 [64 l][72], 9216 -> 15008
#define B_BLO   15008    // feat0 lo bf16, 9216 -> 24224
#define B_EF2   24224    // Ef2 [64 l][68] f32 = 17408 -> 41632
#define B_CP    41632    // colpart [7][68] f32 = 1904 -> 43536
#define B_RED   43536    // 20 f32 -> 43616
#define SMEM_BYTES 43616 // x4 CTAs = 174.5KB

__device__ __forceinline__ uint32_t smem_u32(const void* p) {
    uint32_t a;
    asm("{ .reg .u64 t; cvta.to.shared.u64 t, %1; cvt.u32.u64 %0, t; }"
        : "=r"(a) : "l"(p));
    return a;
}
__device__ __forceinline__ void ldm4(uint32_t addr, uint32_t* r) {
    asm volatile("ldmatrix.sync.aligned.m8n8.x4.shared.b16 {%0,%1,%2,%3}, [%4];"
                 : "=r"(r[0]), "=r"(r[1]), "=r"(r[2]), "=r"(r[3]) : "r"(addr));
}
__device__ __forceinline__ void mma16816(float* d, const uint32_t* a, uint32_t b0, uint32_t b1) {
    asm volatile("mma.sync.aligned.m16n8k16.row.col.f32.bf16.bf16.f32 "
                 "{%0,%1,%2,%3}, {%4,%5,%6,%7}, {%8,%9}, {%0,%1,%2,%3};"
                 : "+f"(d[0]), "+f"(d[1]), "+f"(d[2]), "+f"(d[3])
                 : "r"(a[0]), "r"(a[1]), "r"(a[2]), "r"(a[3]), "r"(b0), "r"(b1));
}
// split (x,y) -> packed bf16 hi pair + packed residual pair (hi halves via shifts)
__device__ __forceinline__ void split2(float x, float y, uint32_t& hi, uint32_t& lo) {
    uint32_t h;
    asm("cvt.rn.bf16x2.f32 %0, %1, %2;" : "=r"(h) : "f"(y), "f"(x));
    float hxf = __uint_as_float(h << 16);
    float hyf = __uint_as_float(h & 0xffff0000u);
    float lx = x - hxf;
    float ly = y - hyf;
    uint32_t l;
    asm("cvt.rn.bf16x2.f32 %0, %1, %2;" : "=r"(l) : "f"(ly), "f"(lx));
    hi = h;
    lo = l;
}
__device__ __forceinline__ float4 ldcs4(const float4* p) {
    float4 v;
    asm volatile("ld.global.cs.v4.f32 {%0,%1,%2,%3}, [%4];"
                 : "=f"(v.x), "=f"(v.y), "=f"(v.z), "=f"(v.w) : "l"(p));
    return v;
}
__device__ __forceinline__ void stcs4(float4* p, float4 v) {
    asm volatile("st.global.cs.v4.f32 [%0], {%1,%2,%3,%4};"
                 :: "l"(p), "f"(v.x), "f"(v.y), "f"(v.z), "f"(v.w) : "memory");
}

__global__ __launch_bounds__(TPB, 4)
void fine_matching_kernel(const float* __restrict__ feat0,
                          const float* __restrict__ feat1,
                          const float* __restrict__ mk0c,
                          const float* __restrict__ mk1c,
                          const int*   __restrict__ hw0i,
                          const int*   __restrict__ hw0f,
                          float* __restrict__ out_mk0,
                          float* __restrict__ out_mk1,
                          float* __restrict__ out_probs,
                          float* __restrict__ out_sm)
{
    extern __shared__ float smem[];
    uint8_t* smb = reinterpret_cast<uint8_t*>(smem);
    const uint32_t sb = smem_u32(smem);

    float* Ef2     = reinterpret_cast<float*>(smb + B_EF2);
    float* Aff     = reinterpret_cast<float*>(smb + B_AFF);
    float* Bff     = reinterpret_cast<float*>(smb + B_BFF);
    float* colpart = reinterpret_cast<float*>(smb + B_CP);
    float* red     = reinterpret_cast<float*>(smb + B_RED);
    int*   ired    = reinterpret_cast<int*>(red);

    const int m    = blockIdx.x;
    const int tid  = threadIdx.x;
    const int wid  = tid >> 5;
    const int lane = tid & 31;
    const int q    = lane >> 2;
    const int c2   = lane & 3;

    const float* A = feat1 + (size_t)m * 6400;

    // ---------------- L2 prefetch of this CTA's feat1 slab (200 x 128B lines) ----------------
    if (tid < 200)
        asm volatile("prefetch.global.L2 [%0];" :: "l"(A + tid * 32));

    const int  r0 = 16 * wid + q;      // warp's A rows: r0, r0+8
    const bool v0 = (wid < 7) && (r0 < 100);
    const bool v1 = (wid < 7) && (r0 + 8 < 100);

    // ks=0 A fragments: hoisted so they're in flight across the stage barrier
    float2 a0h, a1h, a2h, a3h;

    // ---------------- stage: thread owns (row l, 8 channels); STS.128 per tile ----------------
    {
        const float4* f0 = reinterpret_cast<const float4*>(feat0 + (size_t)m * 4096);
        // two tasks per thread: t = tid, tid + 256; task t -> l = t>>3, g = t&7 (ch 8g..8g+7)
        const int t0 = tid,        l0 = t0 >> 3, g0 = t0 & 7;
        const int t1 = tid + 256,  l1 = t1 >> 3, g1 = t1 & 7;
        float4 va0 = ldcs4(&f0[l0 * 16 + 2 * g0]);
        float4 vb0 = ldcs4(&f0[l0 * 16 + 2 * g0 + 1]);
        float4 va1 = ldcs4(&f0[l1 * 16 + 2 * g1]);
        float4 vb1 = ldcs4(&f0[l1 * 16 + 2 * g1 + 1]);

        // ff harvest + ks=0 A fragments (L2-hot) inside feat0's DRAM flight
        {
            const float2 z = make_float2(0.0f, 0.0f);
            float2 w0 = v0 ? *reinterpret_cast<const float2*>(A + r0 * 64 + 56 + 2 * c2) : z;
            float2 w1 = v1 ? *reinterpret_cast<const float2*>(A + (r0 + 8) * 64 + 56 + 2 * c2) : z;
            a0h = v0 ? *reinterpret_cast<const float2*>(A + r0 * 64 + 2 * c2) : z;
            a1h = v1 ? *reinterpret_cast<const float2*>(A + (r0 + 8) * 64 + 2 * c2) : z;
            a2h = v0 ? *reinterpret_cast<const float2*>(A + r0 * 64 + 2 * c2 + 8) : z;
            a3h = v1 ? *reinterpret_cast<const float2*>(A + (r0 + 8) * 64 + 2 * c2 + 8) : z;
            if (v0) {
                Bff[(2 * c2 + 0) * SBF + r0] = w0.x;
                Bff[(2 * c2 + 1) * SBF + r0] = w0.y;
            }
            if (v1) {
                Bff[(2 * c2 + 0) * SBF + r0 + 8] = w1.x;
                Bff[(2 * c2 + 1) * SBF + r0 + 8] = w1.y;
            }
        }

        #pragma unroll
        for (int it = 0; it < 2; it++) {
            int l = it ? l1 : l0, g = it ? g1 : g0;
            float4 va = it ? va1 : va0, vb = it ? vb1 : vb0;
            uint32_t off = (uint32_t)l * BSTR + g * 16;
            if (g < 7) {
                uint32_t h0, p0, h1, p1, h2, p2, h3, p3;
                split2(va.x, va.y, h0, p0);
                split2(va.z, va.w, h1, p1);
                split2(vb.x, vb.y, h2, p2);
                split2(vb.z, vb.w, h3, p3);
                *reinterpret_cast<uint4*>(smb + B_BHI + off) = make_uint4(h0, h1, h2, h3);
                *reinterpret_cast<uint4*>(smb + B_BLO + off) = make_uint4(p0, p1, p2, p3);
            } else {
                *reinterpret_cast<uint4*>(smb + B_BHI + off) = make_uint4(0u, 0u, 0u, 0u);
                *reinterpret_cast<uint4*>(smb + B_BLO + off) = make_uint4(0u, 0u, 0u, 0u);
                Aff[0 * SAF + l] = va.x;
                Aff[1 * SAF + l] = va.y;
                Aff[2 * SAF + l] = va.z;
                Aff[3 * SAF + l] = va.w;
                Aff[4 * SAF + l] = vb.x;
                Aff[5 * SAF + l] = vb.y;
                Aff[6 * SAF + l] = vb.z;
                Aff[7 * SAF + l] = vb.w;
            }
        }
    }
    __syncthreads();

    // ---------------- GEMM: 3 bf16 terms (hh + hl + lh); A per k-step (ks=0 hoisted) ----------------
    float acc[8][4];
    #pragma unroll
    for (int n = 0; n < 8; n++)
        #pragma unroll
        for (int p = 0; p < 4; p++) acc[n][p] = 0.0f;

    if (wid < 7) {
        const uint32_t bLane = (uint32_t)((((lane >> 4) & 1) * 8 + (lane & 7)) * BSTR)
                             + (uint32_t)(((lane >> 3) & 1) * 16);
        const uint32_t Bh = sb + B_BHI + bLane;
        const uint32_t Bl = sb + B_BLO + bLane;
        const float2 z = make_float2(0.0f, 0.0f);
        #pragma unroll
        for (int ks = 0; ks < 4; ks++) {
            float2 a0, a1, a2, a3;
            if (ks == 0) {
                a0 = a0h; a1 = a1h; a2 = a2h; a3 = a3h;
            } else {
                int k0 = 16 * ks + 2 * c2;
                a0 = v0 ? *reinterpret_cast<const float2*>(A + r0 * 64 + k0) : z;
                a1 = v1 ? *reinterpret_cast<const float2*>(A + (r0 + 8) * 64 + k0) : z;
                a2 = (ks < 3 && v0) ? *reinterpret_cast<const float2*>(A + r0 * 64 + k0 + 8) : z;
                a3 = (ks < 3 && v1) ? *reinterpret_cast<const float2*>(A + (r0 + 8) * 64 + k0 + 8) : z;
            }
            uint32_t ah[4], al[4];
            split2(a0.x, a0.y, ah[0], al[0]);
            split2(a1.x, a1.y, ah[1], al[1]);
            split2(a2.x, a2.y, ah[2], al[2]);
            split2(a3.x, a3.y, ah[3], al[3]);
            #pragma unroll
            for (int j2 = 0; j2 < 4; j2++) {
                uint32_t bh[4], bl[4];
                ldm4(Bh + j2 * 16 * BSTR + ks * 32, bh);
                ldm4(Bl + j2 * 16 * BSTR + ks * 32, bl);
                mma16816(acc[2 * j2],     ah, bh[0], bh[1]);
                mma16816(acc[2 * j2 + 1], ah, bh[2], bh[3]);
                mma16816(acc[2 * j2],     ah, bl[0], bl[1]);
                mma16816(acc[2 * j2 + 1], ah, bl[2], bl[3]);
                mma16816(acc[2 * j2],     al, bh[0], bh[1]);
                mma16816(acc[2 * j2 + 1], al, bh[2], bh[3]);
            }
        }
    }

    // ---------------- exp + fused invCol + crop-only transposed Ef2 stores ----------------
    // (no stabilization: shift cancels exactly in the dual-softmax ratio)
    {
        const float inv64 = 1.0f / 64.0f;
        float sa = 0.0f, sbm = 0.0f;
        float t0[8], t1[8];
        #pragma unroll
        for (int n = 0; n < 8; n++) {
            float e0 = 0.0f, e1 = 0.0f, e2 = 0.0f, e3 = 0.0f;
            if (v0) {
                e0 = __expf(acc[n][0] * inv64);
                e1 = __expf(acc[n][1] * inv64);
                sa += e0 + e1;
            }
            if (v1) {
                e2 = __expf(acc[n][2] * inv64);
                e3 = __expf(acc[n][3] * inv64);
                sbm += e2 + e3;
            }
            acc[n][0] = e0; acc[n][1] = e1; acc[n][2] = e2; acc[n][3] = e3;
            t0[n] = e0 + e2;
            t1[n] = e1 + e3;
        }
        sa  += __shfl_xor_sync(0xffffffffu, sa, 1);
        sa  += __shfl_xor_sync(0xffffffffu, sa, 2);
        sbm += __shfl_xor_sync(0xffffffffu, sbm, 1);
        sbm += __shfl_xor_sync(0xffffffffu, sbm, 2);
        const float invc0 = 1.0f / sa;
        const float invc1 = 1.0f / sbm;

        // crop-row mapping: r = 11 + 10i + j (j<8) -> k = 8i + j
        const int  rm0 = r0 - 11;
        const bool cv0 = v0 && rm0 >= 0 && rm0 <= 77 && (rm0 % 10) < 8;
        const int  kc0 = (rm0 / 10) * 8 + (rm0 % 10);
        const int  rm1 = r0 - 3;   // (r0+8) - 11
        const bool cv1 = v1 && rm1 >= 0 && rm1 <= 77 && (rm1 % 10) < 8;
        const int  kc1 = (rm1 / 10) * 8 + (rm1 % 10);

        #pragma unroll
        for (int n = 0; n < 8; n++) {
            int l = 8 * n + 2 * c2;
            if (cv0) {
                Ef2[l * SKE + kc0]       = acc[n][0] * acc[n][0] * invc0;
                Ef2[(l + 1) * SKE + kc0] = acc[n][1] * acc[n][1] * invc0;
            }
            if (cv1) {
                Ef2[l * SKE + kc1]       = acc[n][2] * acc[n][2] * invc1;
                Ef2[(l + 1) * SKE + kc1] = acc[n][3] * acc[n][3] * invc1;
            }
        }

        // column partial sums over this warp's 16 rows (all 100 rows contribute)
        if (wid < 7) {
            #pragma unroll
            for (int off = 4; off <= 16; off <<= 1) {
                #pragma unroll
                for (int n = 0; n < 8; n++) {
                    t0[n] += __shfl_xor_sync(0xffffffffu, t0[n], off);
                    t1[n] += __shfl_xor_sync(0xffffffffu, t1[n], off);
                }
            }
            if (q == 0) {
                #pragma unroll
                for (int n = 0; n < 8; n++)
                    *reinterpret_cast<float2*>(&colpart[wid * SCP + 8 * n + 2 * c2]) =
                        make_float2(t0[n], t1[n]);
            }
        }
    }
    __syncthreads();

    // ---------------- sm output + argmax: thread owns (l = tid>>2, k in 16*(tid&3)..+15) ----------------
    float best = -1.0f;
    int   bidx = 0;
    {
        const int l_sm = tid >> 2;
        const int kb   = (tid & 3) << 4;
        float s = 0.0f;
        #pragma unroll
        for (int w2 = 0; w2 < 7; w2++) s += colpart[w2 * SCP + l_sm];
        const float irow = 1.0f / s;
        float* smo = out_sm + (size_t)m * 4096 + l_sm * 64 + kb;
        const float* erow = &Ef2[l_sm * SKE + kb];
        #pragma unroll
        for (int j = 0; j < 4; j++) {
            float4 v = *reinterpret_cast<const float4*>(erow + 4 * j);
            v.x *= irow; v.y *= irow; v.z *= irow; v.w *= irow;
            stcs4(reinterpret_cast<float4*>(smo + 4 * j), v);
            const float* vp = &v.x;
            #pragma unroll
            for (int i = 0; i < 4; i++) {
                if (vp[i] > best) { best = vp[i]; bidx = l_sm * 64 + kb + 4 * j + i; }
            }
        }
    }
    #pragma unroll
    for (int off = 16; off; off >>= 1) {
        float ov = __shfl_xor_sync(0xffffffffu, best, off);
        int   oi = __shfl_xor_sync(0xffffffffu, bidx, off);
        if (ov > best || (ov == best && oi < bidx)) { best = ov; bidx = oi; }
    }
    if (lane == 0) {
        red[wid] = best;
        ired[8 + wid] = bidx;
    }
    __syncthreads();

    // ---------------- warp 0: final argmax scan + epilogue ----------------
    if (tid < 32) {
        float bv = red[0];
        int   bi = ired[8];
        #pragma unroll
        for (int w2 = 1; w2 < 8; w2++) {
            float ov = red[w2];
            int   oi = ired[8 + w2];
            if (ov > bv || (ov == bv && oi < bi)) { bv = ov; bi = oi; }
        }
        const int idx = bi;
        const int idx_l = idx >> 6;
        const int idx_r = idx & 63;
        const float scl = (float)(*hw0i) / (float)(*hw0f);
        const float rs8 = 0.35355339059327376f;  // 1/sqrt(8)

        const int  di = tid / 3;
        const int  dj = tid - di * 3;
        const bool vv = tid < 9;

        float w = -3.0e38f;
        if (vv) {
            int wi = (idx_r >> 3) + di - 1; if (wi < 0) wi += 10;
            int wj = (idx_r & 7)  + dj - 1; if (wj < 0) wj += 10;
            int wr = wi * 10 + wj;
            float dot = 0.0f;
            #pragma unroll
            for (int c = 0; c < 8; c++)
                dot = fmaf(Aff[c * SAF + idx_l], Bff[c * SBF + wr], dot);
            w = dot * rs8;
        }
        float mx = w;
        #pragma unroll
        for (int off = 16; off; off >>= 1)
            mx = fmaxf(mx, __shfl_xor_sync(0xffffffffu, mx, off));
        float t = vv ? __expf((w - mx) * 0.1f) : 0.0f;   // TEMP = 10
        float s = t;
        #pragma unroll
        for (int off = 16; off; off >>= 1)
            s += __shfl_xor_sync(0xffffffffu, s, off);
        float pr = t / s;
        if (vv) out_probs[(size_t)m * 9 + tid] = pr;

        float cx = vv ? pr * (float)(dj - 1) : 0.0f;
        float cy = vv ? pr * (float)(di - 1) : 0.0f;
        #pragma unroll
        for (int off = 16; off; off >>= 1) {
            cx += __shfl_xor_sync(0xffffffffu, cx, off);
            cy += __shfl_xor_sync(0xffffffffu, cy, off);
        }
        if (tid == 0) {
            float m0x = mk0c[2 * m], m0y = mk0c[2 * m + 1];
            float m1x = mk1c[2 * m], m1y = mk1c[2 * m + 1];
            out_mk0[2 * m]     = fmaf((float)(idx_l & 7) - 3.5f, scl, m0x);
            out_mk0[2 * m + 1] = fmaf((float)(idx_l >> 3) - 3.5f, scl, m0y);
            out_mk1[2 * m]     = m1x + ((float)(idx_r & 7) - 3.5f) * scl + cx * scl;
            out_mk1[2 * m + 1] = m1y + ((float)(idx_r >> 3) - 3.5f) * scl + cy * scl;
        }
    }
}

extern "C" void kernel_launch(void* const* d_in, const int* in_sizes, int n_in,
                              void* d_out, int out_size) {
    const float* feat0 = (const float*)d_in[0];
    const float* feat1 = (const float*)d_in[1];
    const float* mk0c  = (const float*)d_in[2];
    const float* mk1c  = (const float*)d_in[3];
    // d_in[4] = mconf (unused), d_in[5] = b_ids (unused)
    const int* hw0i = (const int*)d_in[6];
    const int* hw0f = (const int*)d_in[7];

    const int M = in_sizes[0] / 4096;

    float* out       = (float*)d_out;
    float* out_mk0   = out;
    float* out_mk1   = out + (size_t)2 * M;
    float* out_probs = out + (size_t)4 * M;
    float* out_sm    = out + (size_t)13 * M;

    cudaFuncSetAttribute(fine_matching_kernel,
                         cudaFuncAttributeMaxDynamicSharedMemorySize, SMEM_BYTES);
    fine_matching_kernel<<<M, TPB, SMEM_BYTES>>>(
        feat0, feat1, mk0c, mk1c, hw0i, hw0f,
        out_mk0, out_mk1, out_probs, out_sm);
}

// round 16
// speedup vs baseline: 1.0105x; 1.0105x over previous
#include <cuda_runtime.h>
#include <cuda_bf16.h>
#include <stdint.h>

// FineMatching R15: R13 + ONLY the ks=0 A-fragment hoist from R14 (cache hints reverted).
// Clean A/B to attribute R14's regression: .cs hints suspected harmful, hoist suspected good.

#define TPB 256
#define SKE 68    // Ef2 stride floats, [l][k] layout
#define SAF 68    // Aff stride floats
#define SBF 113   // Bff stride floats
#define SCP 68    // colpart stride floats
#define BSTR 144  // feat0 bf16 tile row stride bytes (72 b16)

// byte offsets in dynamic smem
#define B_AFF   0        // 8*68*4  = 2176   (feat0 ch 56..63, [c][l])
#define B_BFF   2176     // 8*113*4 = 3616 -> 5792  (feat1 ch 56..63, [c][r])
#define B_BHI   5792     // feat0 hi bf16 [64 l][72], 9216 -> 15008
#define B_BLO   15008    // feat0 lo bf16, 9216 -> 24224
#define B_EF2   24224    // Ef2 [64 l][68] f32 = 17408 -> 41632
#define B_CP    41632    // colpart [7][68] f32 = 1904 -> 43536
#define B_RED   43536    // 20 f32 -> 43616
#define SMEM_BYTES 43616 // x4 CTAs = 174.5KB

__device__ __forceinline__ uint32_t smem_u32(const void* p) {
    uint32_t a;
    asm("{ .reg .u64 t; cvta.to.shared.u64 t, %1; cvt.u32.u64 %0, t; }"
        : "=r"(a) : "l"(p));
    return a;
}
__device__ __forceinline__ void ldm4(uint32_t addr, uint32_t* r) {
    asm volatile("ldmatrix.sync.aligned.m8n8.x4.shared.b16 {%0,%1,%2,%3}, [%4];"
                 : "=r"(r[0]), "=r"(r[1]), "=r"(r[2]), "=r"(r[3]) : "r"(addr));
}
__device__ __forceinline__ void mma16816(float* d, const uint32_t* a, uint32_t b0, uint32_t b1) {
    asm volatile("mma.sync.aligned.m16n8k16.row.col.f32.bf16.bf16.f32 "
                 "{%0,%1,%2,%3}, {%4,%5,%6,%7}, {%8,%9}, {%0,%1,%2,%3};"
                 : "+f"(d[0]), "+f"(d[1]), "+f"(d[2]), "+f"(d[3])
                 : "r"(a[0]), "r"(a[1]), "r"(a[2]), "r"(a[3]), "r"(b0), "r"(b1));
}
// split (x,y) -> packed bf16 hi pair + packed residual pair (hi halves via shifts)
__device__ __forceinline__ void split2(float x, float y, uint32_t& hi, uint32_t& lo) {
    uint32_t h;
    asm("cvt.rn.bf16x2.f32 %0, %1, %2;" : "=r"(h) : "f"(y), "f"(x));
    float hxf = __uint_as_float(h << 16);
    float hyf = __uint_as_float(h & 0xffff0000u);
    float lx = x - hxf;
    float ly = y - hyf;
    uint32_t l;
    asm("cvt.rn.bf16x2.f32 %0, %1, %2;" : "=r"(l) : "f"(ly), "f"(lx));
    hi = h;
    lo = l;
}

__global__ __launch_bounds__(TPB, 4)
void fine_matching_kernel(const float* __restrict__ feat0,
                          const float* __restrict__ feat1,
                          const float* __restrict__ mk0c,
                          const float* __restrict__ mk1c,
                          const int*   __restrict__ hw0i,
                          const int*   __restrict__ hw0f,
                          float* __restrict__ out_mk0,
                          float* __restrict__ out_mk1,
                          float* __restrict__ out_probs,
                          float* __restrict__ out_sm)
{
    extern __shared__ float smem[];
    uint8_t* smb = reinterpret_cast<uint8_t*>(smem);
    const uint32_t sb = smem_u32(smem);

    float* Ef2     = reinterpret_cast<float*>(smb + B_EF2);
    float* Aff     = reinterpret_cast<float*>(smb + B_AFF);
    float* Bff     = reinterpret_cast<float*>(smb + B_BFF);
    float* colpart = reinterpret_cast<float*>(smb + B_CP);
    float* red     = reinterpret_cast<float*>(smb + B_RED);
    int*   ired    = reinterpret_cast<int*>(red);

    const int m    = blockIdx.x;
    const int tid  = threadIdx.x;
    const int wid  = tid >> 5;
    const int lane = tid & 31;
    const int q    = lane >> 2;
    const int c2   = lane & 3;

    const float* A = feat1 + (size_t)m * 6400;

    // ---------------- L2 prefetch of this CTA's feat1 slab (200 x 128B lines) ----------------
    if (tid < 200)
        asm volatile("prefetch.global.L2 [%0];" :: "l"(A + tid * 32));

    const int  r0 = 16 * wid + q;      // warp's A rows: r0, r0+8
    const bool v0 = (wid < 7) && (r0 < 100);
    const bool v1 = (wid < 7) && (r0 + 8 < 100);

    // ks=0 A fragments: hoisted so they're in flight across the stage barrier
    float2 a0h, a1h, a2h, a3h;

    // ---------------- stage: thread owns (row l, 8 channels); STS.128 per tile ----------------
    {
        const float4* f0 = reinterpret_cast<const float4*>(feat0 + (size_t)m * 4096);
        // two tasks per thread: t = tid, tid + 256; task t -> l = t>>3, g = t&7 (ch 8g..8g+7)
        const int t0 = tid,        l0 = t0 >> 3, g0 = t0 & 7;
        const int t1 = tid + 256,  l1 = t1 >> 3, g1 = t1 & 7;
        float4 va0 = f0[l0 * 16 + 2 * g0];
        float4 vb0 = f0[l0 * 16 + 2 * g0 + 1];
        float4 va1 = f0[l1 * 16 + 2 * g1];
        float4 vb1 = f0[l1 * 16 + 2 * g1 + 1];

        // ff harvest + ks=0 A fragments (L2-hot) inside feat0's DRAM flight
        {
            const float2 z = make_float2(0.0f, 0.0f);
            float2 w0 = v0 ? *reinterpret_cast<const float2*>(A + r0 * 64 + 56 + 2 * c2) : z;
            float2 w1 = v1 ? *reinterpret_cast<const float2*>(A + (r0 + 8) * 64 + 56 + 2 * c2) : z;
            a0h = v0 ? *reinterpret_cast<const float2*>(A + r0 * 64 + 2 * c2) : z;
            a1h = v1 ? *reinterpret_cast<const float2*>(A + (r0 + 8) * 64 + 2 * c2) : z;
            a2h = v0 ? *reinterpret_cast<const float2*>(A + r0 * 64 + 2 * c2 + 8) : z;
            a3h = v1 ? *reinterpret_cast<const float2*>(A + (r0 + 8) * 64 + 2 * c2 + 8) : z;
            if (v0) {
                Bff[(2 * c2 + 0) * SBF + r0] = w0.x;
                Bff[(2 * c2 + 1) * SBF + r0] = w0.y;
            }
            if (v1) {
                Bff[(2 * c2 + 0) * SBF + r0 + 8] = w1.x;
                Bff[(2 * c2 + 1) * SBF + r0 + 8] = w1.y;
            }
        }

        #pragma unroll
        for (int it = 0; it < 2; it++) {
            int l = it ? l1 : l0, g = it ? g1 : g0;
            float4 va = it ? va1 : va0, vb = it ? vb1 : vb0;
            uint32_t off = (uint32_t)l * BSTR + g * 16;
            if (g < 7) {
                uint32_t h0, p0, h1, p1, h2, p2, h3, p3;
                split2(va.x, va.y, h0, p0);
                split2(va.z, va.w, h1, p1);
                split2(vb.x, vb.y, h2, p2);
                split2(vb.z, vb.w, h3, p3);
                *reinterpret_cast<uint4*>(smb + B_BHI + off) = make_uint4(h0, h1, h2, h3);
                *reinterpret_cast<uint4*>(smb + B_BLO + off) = make_uint4(p0, p1, p2, p3);
            } else {
                *reinterpret_cast<uint4*>(smb + B_BHI + off) = make_uint4(0u, 0u, 0u, 0u);
                *reinterpret_cast<uint4*>(smb + B_BLO + off) = make_uint4(0u, 0u, 0u, 0u);
                Aff[0 * SAF + l] = va.x;
                Aff[1 * SAF + l] = va.y;
                Aff[2 * SAF + l] = va.z;
                Aff[3 * SAF + l] = va.w;
                Aff[4 * SAF + l] = vb.x;
                Aff[5 * SAF + l] = vb.y;
                Aff[6 * SAF + l] = vb.z;
                Aff[7 * SAF + l] = vb.w;
            }
        }
    }
    __syncthreads();

    // ---------------- GEMM: 3 bf16 terms (hh + hl + lh); A per k-step (ks=0 hoisted) ----------------
    float acc[8][4];
    #pragma unroll
    for (int n = 0; n < 8; n++)
        #pragma unroll
        for (int p = 0; p < 4; p++) acc[n][p] = 0.0f;

    if (wid < 7) {
        const uint32_t bLane = (uint32_t)((((lane >> 4) & 1) * 8 + (lane & 7)) * BSTR)
                             + (uint32_t)(((lane >> 3) & 1) * 16);
        const uint32_t Bh = sb + B_BHI + bLane;
        const uint32_t Bl = sb + B_BLO + bLane;
        const float2 z = make_float2(0.0f, 0.0f);
        #pragma unroll
        for (int ks = 0; ks < 4; ks++) {
            float2 a0, a1, a2, a3;
            if (ks == 0) {
                a0 = a0h; a1 = a1h; a2 = a2h; a3 = a3h;
            } else {
                int k0 = 16 * ks + 2 * c2;
                a0 = v0 ? *reinterpret_cast<const float2*>(A + r0 * 64 + k0) : z;
                a1 = v1 ? *reinterpret_cast<const float2*>(A + (r0 + 8) * 64 + k0) : z;
                a2 = (ks < 3 && v0) ? *reinterpret_cast<const float2*>(A + r0 * 64 + k0 + 8) : z;
                a3 = (ks < 3 && v1) ? *reinterpret_cast<const float2*>(A + (r0 + 8) * 64 + k0 + 8) : z;
            }
            uint32_t ah[4], al[4];
            split2(a0.x, a0.y, ah[0], al[0]);
            split2(a1.x, a1.y, ah[1], al[1]);
            split2(a2.x, a2.y, ah[2], al[2]);
            split2(a3.x, a3.y, ah[3], al[3]);
            #pragma unroll
            for (int j2 = 0; j2 < 4; j2++) {
                uint32_t bh[4], bl[4];
                ldm4(Bh + j2 * 16 * BSTR + ks * 32, bh);
                ldm4(Bl + j2 * 16 * BSTR + ks * 32, bl);
                mma16816(acc[2 * j2],     ah, bh[0], bh[1]);
                mma16816(acc[2 * j2 + 1], ah, bh[2], bh[3]);
                mma16816(acc[2 * j2],     ah, bl[0], bl[1]);
                mma16816(acc[2 * j2 + 1], ah, bl[2], bl[3]);
                mma16816(acc[2 * j2],     al, bh[0], bh[1]);
                mma16816(acc[2 * j2 + 1], al, bh[2], bh[3]);
            }
        }
    }

    // ---------------- exp + fused invCol + crop-only transposed Ef2 stores ----------------
    // (no stabilization: shift cancels exactly in the dual-softmax ratio)
    {
        const float inv64 = 1.0f / 64.0f;
        float sa = 0.0f, sbm = 0.0f;
        float t0[8], t1[8];
        #pragma unroll
        for (int n = 0; n < 8; n++) {
            float e0 = 0.0f, e1 = 0.0f, e2 = 0.0f, e3 = 0.0f;
            if (v0) {
                e0 = __expf(acc[n][0] * inv64);
                e1 = __expf(acc[n][1] * inv64);
                sa += e0 + e1;
            }
            if (v1) {
                e2 = __expf(acc[n][2] * inv64);
                e3 = __expf(acc[n][3] * inv64);
                sbm += e2 + e3;
            }
            acc[n][0] = e0; acc[n][1] = e1; acc[n][2] = e2; acc[n][3] = e3;
            t0[n] = e0 + e2;
            t1[n] = e1 + e3;
        }
        sa  += __shfl_xor_sync(0xffffffffu, sa, 1);
        sa  += __shfl_xor_sync(0xffffffffu, sa, 2);
        sbm += __shfl_xor_sync(0xffffffffu, sbm, 1);
        sbm += __shfl_xor_sync(0xffffffffu, sbm, 2);
        const float invc0 = 1.0f / sa;
        const float invc1 = 1.0f / sbm;

        // crop-row mapping: r = 11 + 10i + j (j<8) -> k = 8i + j
        const int  rm0 = r0 - 11;
        const bool cv0 = v0 && rm0 >= 0 && rm0 <= 77 && (rm0 % 10) < 8;
        const int  kc0 = (rm0 / 10) * 8 + (rm0 % 10);
        const int  rm1 = r0 - 3;   // (r0+8) - 11
        const bool cv1 = v1 && rm1 >= 0 && rm1 <= 77 && (rm1 % 10) < 8;
        const int  kc1 = (rm1 / 10) * 8 + (rm1 % 10);

        #pragma unroll
        for (int n = 0; n < 8; n++) {
            int l = 8 * n + 2 * c2;
            if (cv0) {
                Ef2[l * SKE + kc0]       = acc[n][0] * acc[n][0] * invc0;
                Ef2[(l + 1) * SKE + kc0] = acc[n][1] * acc[n][1] * invc0;
            }
            if (cv1) {
                Ef2[l * SKE + kc1]       = acc[n][2] * acc[n][2] * invc1;
                Ef2[(l + 1) * SKE + kc1] = acc[n][3] * acc[n][3] * invc1;
            }
        }

        // column partial sums over this warp's 16 rows (all 100 rows contribute)
        if (wid < 7) {
            #pragma unroll
            for (int off = 4; off <= 16; off <<= 1) {
                #pragma unroll
                for (int n = 0; n < 8; n++) {
                    t0[n] += __shfl_xor_sync(0xffffffffu, t0[n], off);
                    t1[n] += __shfl_xor_sync(0xffffffffu, t1[n], off);
                }
            }
            if (q == 0) {
                #pragma unroll
                for (int n = 0; n < 8; n++)
                    *reinterpret_cast<float2*>(&colpart[wid * SCP + 8 * n + 2 * c2]) =
                        make_float2(t0[n], t1[n]);
            }
        }
    }
    __syncthreads();

    // ---------------- sm output + argmax: thread owns (l = tid>>2, k in 16*(tid&3)..+15) ----------------
    float best = -1.0f;
    int   bidx = 0;
    {
        const int l_sm = tid >> 2;
        const int kb   = (tid & 3) << 4;
        float s = 0.0f;
        #pragma unroll
        for (int w2 = 0; w2 < 7; w2++) s += colpart[w2 * SCP + l_sm];
        const float irow = 1.0f / s;
        float* smo = out_sm + (size_t)m * 4096 + l_sm * 64 + kb;
        const float* erow = &Ef2[l_sm * SKE + kb];
        #pragma unroll
        for (int j = 0; j < 4; j++) {
            float4 v = *reinterpret_cast<const float4*>(erow + 4 * j);
            v.x *= irow; v.y *= irow; v.z *= irow; v.w *= irow;
            *reinterpret_cast<float4*>(smo + 4 * j) = v;
            const float* vp = &v.x;
            #pragma unroll
            for (int i = 0; i < 4; i++) {
                if (vp[i] > best) { best = vp[i]; bidx = l_sm * 64 + kb + 4 * j + i; }
            }
        }
    }
    #pragma unroll
    for (int off = 16; off; off >>= 1) {
        float ov = __shfl_xor_sync(0xffffffffu, best, off);
        int   oi = __shfl_xor_sync(0xffffffffu, bidx, off);
        if (ov > best || (ov == best && oi < bidx)) { best = ov; bidx = oi; }
    }
    if (lane == 0) {
        red[wid] = best;
        ired[8 + wid] = bidx;
    }
    __syncthreads();

    // ---------------- warp 0: final argmax scan + epilogue ----------------
    if (tid < 32) {
        float bv = red[0];
        int   bi = ired[8];
        #pragma unroll
        for (int w2 = 1; w2 < 8; w2++) {
            float ov = red[w2];
            int   oi = ired[8 + w2];
            if (ov > bv || (ov == bv && oi < bi)) { bv = ov; bi = oi; }
        }
        const int idx = bi;
        const int idx_l = idx >> 6;
        const int idx_r = idx & 63;
        const float scl = (float)(*hw0i) / (float)(*hw0f);
        const float rs8 = 0.35355339059327376f;  // 1/sqrt(8)

        const int  di = tid / 3;
        const int  dj = tid - di * 3;
        const bool vv = tid < 9;

        float w = -3.0e38f;
        if (vv) {
            int wi = (idx_r >> 3) + di - 1; if (wi < 0) wi += 10;
            int wj = (idx_r & 7)  + dj - 1; if (wj < 0) wj += 10;
            int wr = wi * 10 + wj;
            float dot = 0.0f;
            #pragma unroll
            for (int c = 0; c < 8; c++)
                dot = fmaf(Aff[c * SAF + idx_l], Bff[c * SBF + wr], dot);
            w = dot * rs8;
        }
        float mx = w;
        #pragma unroll
        for (int off = 16; off; off >>= 1)
            mx = fmaxf(mx, __shfl_xor_sync(0xffffffffu, mx, off));
        float t = vv ? __expf((w - mx) * 0.1f) : 0.0f;   // TEMP = 10
        float s = t;
        #pragma unroll
        for (int off = 16; off; off >>= 1)
            s += __shfl_xor_sync(0xffffffffu, s, off);
        float pr = t / s;
        if (vv) out_probs[(size_t)m * 9 + tid] = pr;

        float cx = vv ? pr * (float)(dj - 1) : 0.0f;
        float cy = vv ? pr * (float)(di - 1) : 0.0f;
        #pragma unroll
        for (int off = 16; off; off >>= 1) {
            cx += __shfl_xor_sync(0xffffffffu, cx, off);
            cy += __shfl_xor_sync(0xffffffffu, cy, off);
        }
        if (tid == 0) {
            float m0x = mk0c[2 * m], m0y = mk0c[2 * m + 1];
            float m1x = mk1c[2 * m], m1y = mk1c[2 * m + 1];
            out_mk0[2 * m]     = fmaf((float)(idx_l & 7) - 3.5f, scl, m0x);
            out_mk0[2 * m + 1] = fmaf((float)(idx_l >> 3) - 3.5f, scl, m0y);
            out_mk1[2 * m]     = m1x + ((float)(idx_r & 7) - 3.5f) * scl + cx * scl;
            out_mk1[2 * m + 1] = m1y + ((float)(idx_r >> 3) - 3.5f) * scl + cy * scl;
        }
    }
}

extern "C" void kernel_launch(void* const* d_in, const int* in_sizes, int n_in,
                              void* d_out, int out_size) {
    const float* feat0 = (const float*)d_in[0];
    const float* feat1 = (const float*)d_in[1];
    const float* mk0c  = (const float*)d_in[2];
    const float* mk1c  = (const float*)d_in[3];
    // d_in[4] = mconf (unused), d_in[5] = b_ids (unused)
    const int* hw0i = (const int*)d_in[6];
    const int* hw0f = (const int*)d_in[7];

    const int M = in_sizes[0] / 4096;

    float* out       = (float*)d_out;
    float* out_mk0   = out;
    float* out_mk1   = out + (size_t)2 * M;
    float* out_probs = out + (size_t)4 * M;
    float* out_sm    = out + (size_t)13 * M;

    cudaFuncSetAttribute(fine_matching_kernel,
                         cudaFuncAttributeMaxDynamicSharedMemorySize, SMEM_BYTES);
    fine_matching_kernel<<<M, TPB, SMEM_BYTES>>>(
        feat0, feat1, mk0c, mk1c, hw0i, hw0f,
        out_mk0, out_mk1, out_probs, out_sm);
}

// round 17
// speedup vs baseline: 1.0236x; 1.0130x over previous
#include <cuda_runtime.h>
#include <cuda_bf16.h>
#include <stdint.h>

// FineMatching R16: R13 verbatim (verified best, 159.9us) + ONE change:
// feat1 L2 prefetch upgraded to ::evict_last, pinning the slab against eviction
// by concurrent CTAs' feat0/out_sm streams until the GEMM A-loads consume it.

#define TPB 256
#define SKE 68    // Ef2 stride floats, [l][k] layout
#define SAF 68    // Aff stride floats
#define SBF 113   // Bff stride floats
#define SCP 68    // colpart stride floats
#define BSTR 144  // feat0 bf16 tile row stride bytes (72 b16)

// byte offsets in dynamic smem
#define B_AFF   0        // 8*68*4  = 2176   (feat0 ch 56..63, [c][l])
#define B_BFF   2176     // 8*113*4 = 3616 -> 5792  (feat1 ch 56..63, [c][r])
#define B_BHI   5792     // feat0 hi bf16 [64 l][72], 9216 -> 15008
#define B_BLO   15008    // feat0 lo bf16, 9216 -> 24224
#define B_EF2   24224    // Ef2 [64 l][68] f32 = 17408 -> 41632
#define B_CP    41632    // colpart [7][68] f32 = 1904 -> 43536
#define B_RED   43536    // 20 f32 -> 43616
#define SMEM_BYTES 43616 // x4 CTAs = 174.5KB

__device__ __forceinline__ uint32_t smem_u32(const void* p) {
    uint32_t a;
    asm("{ .reg .u64 t; cvta.to.shared.u64 t, %1; cvt.u32.u64 %0, t; }"
        : "=r"(a) : "l"(p));
    return a;
}
__device__ __forceinline__ void ldm4(uint32_t addr, uint32_t* r) {
    asm volatile("ldmatrix.sync.aligned.m8n8.x4.shared.b16 {%0,%1,%2,%3}, [%4];"
                 : "=r"(r[0]), "=r"(r[1]), "=r"(r[2]), "=r"(r[3]) : "r"(addr));
}
__device__ __forceinline__ void mma16816(float* d, const uint32_t* a, uint32_t b0, uint32_t b1) {
    asm volatile("mma.sync.aligned.m16n8k16.row.col.f32.bf16.bf16.f32 "
                 "{%0,%1,%2,%3}, {%4,%5,%6,%7}, {%8,%9}, {%0,%1,%2,%3};"
                 : "+f"(d[0]), "+f"(d[1]), "+f"(d[2]), "+f"(d[3])
                 : "r"(a[0]), "r"(a[1]), "r"(a[2]), "r"(a[3]), "r"(b0), "r"(b1));
}
// split (x,y) -> packed bf16 hi pair + packed residual pair (hi halves via shifts)
__device__ __forceinline__ void split2(float x, float y, uint32_t& hi, uint32_t& lo) {
    uint32_t h;
    asm("cvt.rn.bf16x2.f32 %0, %1, %2;" : "=r"(h) : "f"(y), "f"(x));
    float hxf = __uint_as_float(h << 16);
    float hyf = __uint_as_float(h & 0xffff0000u);
    float lx = x - hxf;
    float ly = y - hyf;
    uint32_t l;
    asm("cvt.rn.bf16x2.f32 %0, %1, %2;" : "=r"(l) : "f"(ly), "f"(lx));
    hi = h;
    lo = l;
}

__global__ __launch_bounds__(TPB, 4)
void fine_matching_kernel(const float* __restrict__ feat0,
                          const float* __restrict__ feat1,
                          const float* __restrict__ mk0c,
                          const float* __restrict__ mk1c,
                          const int*   __restrict__ hw0i,
                          const int*   __restrict__ hw0f,
                          float* __restrict__ out_mk0,
                          float* __restrict__ out_mk1,
                          float* __restrict__ out_probs,
                          float* __restrict__ out_sm)
{
    extern __shared__ float smem[];
    uint8_t* smb = reinterpret_cast<uint8_t*>(smem);
    const uint32_t sb = smem_u32(smem);

    float* Ef2     = reinterpret_cast<float*>(smb + B_EF2);
    float* Aff     = reinterpret_cast<float*>(smb + B_AFF);
    float* Bff     = reinterpret_cast<float*>(smb + B_BFF);
    float* colpart = reinterpret_cast<float*>(smb + B_CP);
    float* red     = reinterpret_cast<float*>(smb + B_RED);
    int*   ired    = reinterpret_cast<int*>(red);

    const int m    = blockIdx.x;
    const int tid  = threadIdx.x;
    const int wid  = tid >> 5;
    const int lane = tid & 31;
    const int q    = lane >> 2;
    const int c2   = lane & 3;

    const float* A = feat1 + (size_t)m * 6400;

    // ---------------- L2 prefetch (evict_last: pin against streaming eviction) ----------------
    if (tid < 200)
        asm volatile("prefetch.global.L2::evict_last [%0];" :: "l"(A + tid * 32));

    const int  r0 = 16 * wid + q;      // warp's A rows: r0, r0+8
    const bool v0 = (wid < 7) && (r0 < 100);
    const bool v1 = (wid < 7) && (r0 + 8 < 100);

    // ---------------- stage: thread owns (row l, 8 channels); STS.128 per tile ----------------
    {
        const float4* f0 = reinterpret_cast<const float4*>(feat0 + (size_t)m * 4096);
        // two tasks per thread: t = tid, tid + 256; task t -> l = t>>3, g = t&7 (ch 8g..8g+7)
        const int t0 = tid,        l0 = t0 >> 3, g0 = t0 & 7;
        const int t1 = tid + 256,  l1 = t1 >> 3, g1 = t1 & 7;
        float4 va0 = f0[l0 * 16 + 2 * g0];
        float4 vb0 = f0[l0 * 16 + 2 * g0 + 1];
        float4 va1 = f0[l1 * 16 + 2 * g1];
        float4 vb1 = f0[l1 * 16 + 2 * g1 + 1];

        // ff harvest (L2-hot) inside feat0's DRAM flight
        {
            const float2 z = make_float2(0.0f, 0.0f);
            float2 w0 = v0 ? *reinterpret_cast<const float2*>(A + r0 * 64 + 56 + 2 * c2) : z;
            float2 w1 = v1 ? *reinterpret_cast<const float2*>(A + (r0 + 8) * 64 + 56 + 2 * c2) : z;
            if (v0) {
                Bff[(2 * c2 + 0) * SBF + r0] = w0.x;
                Bff[(2 * c2 + 1) * SBF + r0] = w0.y;
            }
            if (v1) {
                Bff[(2 * c2 + 0) * SBF + r0 + 8] = w1.x;
                Bff[(2 * c2 + 1) * SBF + r0 + 8] = w1.y;
            }
        }

        #pragma unroll
        for (int it = 0; it < 2; it++) {
            int l = it ? l1 : l0, g = it ? g1 : g0;
            float4 va = it ? va1 : va0, vb = it ? vb1 : vb0;
            uint32_t off = (uint32_t)l * BSTR + g * 16;
            if (g < 7) {
                uint32_t h0, p0, h1, p1, h2, p2, h3, p3;
                split2(va.x, va.y, h0, p0);
                split2(va.z, va.w, h1, p1);
                split2(vb.x, vb.y, h2, p2);
                split2(vb.z, vb.w, h3, p3);
                *reinterpret_cast<uint4*>(smb + B_BHI + off) = make_uint4(h0, h1, h2, h3);
                *reinterpret_cast<uint4*>(smb + B_BLO + off) = make_uint4(p0, p1, p2, p3);
            } else {
                *reinterpret_cast<uint4*>(smb + B_BHI + off) = make_uint4(0u, 0u, 0u, 0u);
                *reinterpret_cast<uint4*>(smb + B_BLO + off) = make_uint4(0u, 0u, 0u, 0u);
                Aff[0 * SAF + l] = va.x;
                Aff[1 * SAF + l] = va.y;
                Aff[2 * SAF + l] = va.z;
                Aff[3 * SAF + l] = va.w;
                Aff[4 * SAF + l] = vb.x;
                Aff[5 * SAF + l] = vb.y;
                Aff[6 * SAF + l] = vb.z;
                Aff[7 * SAF + l] = vb.w;
            }
        }
    }
    __syncthreads();

    // ---------------- GEMM: 3 bf16 terms (hh + hl + lh); A loaded per k-step (L2-hot) ----------------
    float acc[8][4];
    #pragma unroll
    for (int n = 0; n < 8; n++)
        #pragma unroll
        for (int p = 0; p < 4; p++) acc[n][p] = 0.0f;

    if (wid < 7) {
        const uint32_t bLane = (uint32_t)((((lane >> 4) & 1) * 8 + (lane & 7)) * BSTR)
                             + (uint32_t)(((lane >> 3) & 1) * 16);
        const uint32_t Bh = sb + B_BHI + bLane;
        const uint32_t Bl = sb + B_BLO + bLane;
        const float2 z = make_float2(0.0f, 0.0f);
        #pragma unroll
        for (int ks = 0; ks < 4; ks++) {
            int k0 = 16 * ks + 2 * c2;
            float2 a0 = v0 ? *reinterpret_cast<const float2*>(A + r0 * 64 + k0) : z;
            float2 a1 = v1 ? *reinterpret_cast<const float2*>(A + (r0 + 8) * 64 + k0) : z;
            float2 a2 = (ks < 3 && v0) ? *reinterpret_cast<const float2*>(A + r0 * 64 + k0 + 8) : z;
            float2 a3 = (ks < 3 && v1) ? *reinterpret_cast<const float2*>(A + (r0 + 8) * 64 + k0 + 8) : z;
            uint32_t ah[4], al[4];
            split2(a0.x, a0.y, ah[0], al[0]);
            split2(a1.x, a1.y, ah[1], al[1]);
            split2(a2.x, a2.y, ah[2], al[2]);
            split2(a3.x, a3.y, ah[3], al[3]);
            #pragma unroll
            for (int j2 = 0; j2 < 4; j2++) {
                uint32_t bh[4], bl[4];
                ldm4(Bh + j2 * 16 * BSTR + ks * 32, bh);
                ldm4(Bl + j2 * 16 * BSTR + ks * 32, bl);
                mma16816(acc[2 * j2],     ah, bh[0], bh[1]);
                mma16816(acc[2 * j2 + 1], ah, bh[2], bh[3]);
                mma16816(acc[2 * j2],     ah, bl[0], bl[1]);
                mma16816(acc[2 * j2 + 1], ah, bl[2], bl[3]);
                mma16816(acc[2 * j2],     al, bh[0], bh[1]);
                mma16816(acc[2 * j2 + 1], al, bh[2], bh[3]);
            }
        }
    }

    // ---------------- exp + fused invCol + crop-only transposed Ef2 stores ----------------
    // (no stabilization: shift cancels exactly in the dual-softmax ratio)
    {
        const float inv64 = 1.0f / 64.0f;
        float sa = 0.0f, sbm = 0.0f;
        float t0[8], t1[8];
        #pragma unroll
        for (int n = 0; n < 8; n++) {
            float e0 = 0.0f, e1 = 0.0f, e2 = 0.0f, e3 = 0.0f;
            if (v0) {
                e0 = __expf(acc[n][0] * inv64);
                e1 = __expf(acc[n][1] * inv64);
                sa += e0 + e1;
            }
            if (v1) {
                e2 = __expf(acc[n][2] * inv64);
                e3 = __expf(acc[n][3] * inv64);
                sbm += e2 + e3;
            }
            acc[n][0] = e0; acc[n][1] = e1; acc[n][2] = e2; acc[n][3] = e3;
            t0[n] = e0 + e2;
            t1[n] = e1 + e3;
        }
        sa  += __shfl_xor_sync(0xffffffffu, sa, 1);
        sa  += __shfl_xor_sync(0xffffffffu, sa, 2);
        sbm += __shfl_xor_sync(0xffffffffu, sbm, 1);
        sbm += __shfl_xor_sync(0xffffffffu, sbm, 2);
        const float invc0 = 1.0f / sa;
        const float invc1 = 1.0f / sbm;

        // crop-row mapping: r = 11 + 10i + j (j<8) -> k = 8i + j
        const int  rm0 = r0 - 11;
        const bool cv0 = v0 && rm0 >= 0 && rm0 <= 77 && (rm0 % 10) < 8;
        const int  kc0 = (rm0 / 10) * 8 + (rm0 % 10);
        const int  rm1 = r0 - 3;   // (r0+8) - 11
        const bool cv1 = v1 && rm1 >= 0 && rm1 <= 77 && (rm1 % 10) < 8;
        const int  kc1 = (rm1 / 10) * 8 + (rm1 % 10);

        #pragma unroll
        for (int n = 0; n < 8; n++) {
            int l = 8 * n + 2 * c2;
            if (cv0) {
                Ef2[l * SKE + kc0]       = acc[n][0] * acc[n][0] * invc0;
                Ef2[(l + 1) * SKE + kc0] = acc[n][1] * acc[n][1] * invc0;
            }
            if (cv1) {
                Ef2[l * SKE + kc1]       = acc[n][2] * acc[n][2] * invc1;
                Ef2[(l + 1) * SKE + kc1] = acc[n][3] * acc[n][3] * invc1;
            }
        }

        // column partial sums over this warp's 16 rows (all 100 rows contribute)
        if (wid < 7) {
            #pragma unroll
            for (int off = 4; off <= 16; off <<= 1) {
                #pragma unroll
                for (int n = 0; n < 8; n++) {
                    t0[n] += __shfl_xor_sync(0xffffffffu, t0[n], off);
                    t1[n] += __shfl_xor_sync(0xffffffffu, t1[n], off);
                }
            }
            if (q == 0) {
                #pragma unroll
                for (int n = 0; n < 8; n++)
                    *reinterpret_cast<float2*>(&colpart[wid * SCP + 8 * n + 2 * c2]) =
                        make_float2(t0[n], t1[n]);
            }
        }
    }
    __syncthreads();

    // ---------------- sm output + argmax: thread owns (l = tid>>2, k in 16*(tid&3)..+15) ----------------
    float best = -1.0f;
    int   bidx = 0;
    {
        const int l_sm = tid >> 2;
        const int kb   = (tid & 3) << 4;
        float s = 0.0f;
        #pragma unroll
        for (int w2 = 0; w2 < 7; w2++) s += colpart[w2 * SCP + l_sm];
        const float irow = 1.0f / s;
        float* smo = out_sm + (size_t)m * 4096 + l_sm * 64 + kb;
        const float* erow = &Ef2[l_sm * SKE + kb];
        #pragma unroll
        for (int j = 0; j < 4; j++) {
            float4 v = *reinterpret_cast<const float4*>(erow + 4 * j);
            v.x *= irow; v.y *= irow; v.z *= irow; v.w *= irow;
            *reinterpret_cast<float4*>(smo + 4 * j) = v;
            const float* vp = &v.x;
            #pragma unroll
            for (int i = 0; i < 4; i++) {
                if (vp[i] > best) { best = vp[i]; bidx = l_sm * 64 + kb + 4 * j + i; }
            }
        }
    }
    #pragma unroll
    for (int off = 16; off; off >>= 1) {
        float ov = __shfl_xor_sync(0xffffffffu, best, off);
        int   oi = __shfl_xor_sync(0xffffffffu, bidx, off);
        if (ov > best || (ov == best && oi < bidx)) { best = ov; bidx = oi; }
    }
    if (lane == 0) {
        red[wid] = best;
        ired[8 + wid] = bidx;
    }
    __syncthreads();

    // ---------------- warp 0: final argmax scan + epilogue ----------------
    if (tid < 32) {
        float bv = red[0];
        int   bi = ired[8];
        #pragma unroll
        for (int w2 = 1; w2 < 8; w2++) {
            float ov = red[w2];
            int   oi = ired[8 + w2];
            if (ov > bv || (ov == bv && oi < bi)) { bv = ov; bi = oi; }
        }
        const int idx = bi;
        const int idx_l = idx >> 6;
        const int idx_r = idx & 63;
        const float scl = (float)(*hw0i) / (float)(*hw0f);
        const float rs8 = 0.35355339059327376f;  // 1/sqrt(8)

        const int  di = tid / 3;
        const int  dj = tid - di * 3;
        const bool vv = tid < 9;

        float w = -3.0e38f;
        if (vv) {
            int wi = (idx_r >> 3) + di - 1; if (wi < 0) wi += 10;
            int wj = (idx_r & 7)  + dj - 1; if (wj < 0) wj += 10;
            int wr = wi * 10 + wj;
            float dot = 0.0f;
            #pragma unroll
            for (int c = 0; c < 8; c++)
                dot = fmaf(Aff[c * SAF + idx_l], Bff[c * SBF + wr], dot);
            w = dot * rs8;
        }
        float mx = w;
        #pragma unroll
        for (int off = 16; off; off >>= 1)
            mx = fmaxf(mx, __shfl_xor_sync(0xffffffffu, mx, off));
        float t = vv ? __expf((w - mx) * 0.1f) : 0.0f;   // TEMP = 10
        float s = t;
        #pragma unroll
        for (int off = 16; off; off >>= 1)
            s += __shfl_xor_sync(0xffffffffu, s, off);
        float pr = t / s;
        if (vv) out_probs[(size_t)m * 9 + tid] = pr;

        float cx = vv ? pr * (float)(dj - 1) : 0.0f;
        float cy = vv ? pr * (float)(di - 1) : 0.0f;
        #pragma unroll
        for (int off = 16; off; off >>= 1) {
            cx += __shfl_xor_sync(0xffffffffu, cx, off);
            cy += __shfl_xor_sync(0xffffffffu, cy, off);
        }
        if (tid == 0) {
            float m0x = mk0c[2 * m], m0y = mk0c[2 * m + 1];
            float m1x = mk1c[2 * m], m1y = mk1c[2 * m + 1];
            out_mk0[2 * m]     = fmaf((float)(idx_l & 7) - 3.5f, scl, m0x);
            out_mk0[2 * m + 1] = fmaf((float)(idx_l >> 3) - 3.5f, scl, m0y);
            out_mk1[2 * m]     = m1x + ((float)(idx_r & 7) - 3.5f) * scl + cx * scl;
            out_mk1[2 * m + 1] = m1y + ((float)(idx_r >> 3) - 3.5f) * scl + cy * scl;
        }
    }
}

extern "C" void kernel_launch(void* const* d_in, const int* in_sizes, int n_in,
                              void* d_out, int out_size) {
    const float* feat0 = (const float*)d_in[0];
    const float* feat1 = (const float*)d_in[1];
    const float* mk0c  = (const float*)d_in[2];
    const float* mk1c  = (const float*)d_in[3];
    // d_in[4] = mconf (unused), d_in[5] = b_ids (unused)
    const int* hw0i = (const int*)d_in[6];
    const int* hw0f = (const int*)d_in[7];

    const int M = in_sizes[0] / 4096;

    float* out       = (float*)d_out;
    float* out_mk0   = out;
    float* out_mk1   = out + (size_t)2 * M;
    float* out_probs = out + (size_t)4 * M;
    float* out_sm    = out + (size_t)13 * M;

    cudaFuncSetAttribute(fine_matching_kernel,
                         cudaFuncAttributeMaxDynamicSharedMemorySize, SMEM_BYTES);
    fine_matching_kernel<<<M, TPB, SMEM_BYTES>>>(
        feat0, feat1, mk0c, mk1c, hw0i, hw0f,
        out_mk0, out_mk1, out_probs, out_sm);
}